// round 1
// baseline (speedup 1.0000x reference)
#include <cuda_runtime.h>

#define NR 2097152              // rows
#define K  7                    // clusters
#define TPB 256
#define NBLOCKS 1024
#define NTHREADS (NBLOCKS * TPB)    // 262144
#define REPS (NR / NTHREADS)        // 8 rows per thread, exact

// E stored column-major: g_E[j*NR + i]  -> perfectly coalesced 32-bit loads
static __device__ float    g_E[(size_t)NR * K];
static __device__ double   g_S[K];        // reduction accumulators T_j
static __device__ double   g_b[K];        // current b (double, for exact err/pow)
static __device__ float    g_fb[K];       // float copy of b for bulk kernels
static __device__ float    g_fbprev[K];   // b from previous iteration (for final plan)
static __device__ int      g_conv;        // convergence flag
static __device__ unsigned g_done;        // last-block counter

__constant__ double c_Pb[K] = {0.17, 0.14, 0.15, 0.12, 0.05, 0.13, 0.24};

// ---------------------------------------------------------------------------
// Block reduction of K float partials -> double -> atomicAdd into g_S
// ---------------------------------------------------------------------------
__device__ __forceinline__ void block_reduce_atomic(float acc[K]) {
#pragma unroll
    for (int j = 0; j < K; j++) {
#pragma unroll
        for (int off = 16; off > 0; off >>= 1)
            acc[j] += __shfl_down_sync(0xffffffffu, acc[j], off);
    }
    __shared__ double sm[TPB / 32][K];
    int w = threadIdx.x >> 5;
    if ((threadIdx.x & 31) == 0) {
#pragma unroll
        for (int j = 0; j < K; j++) sm[w][j] = (double)acc[j];
    }
    __syncthreads();
    if (threadIdx.x < K) {
        double s = 0.0;
#pragma unroll
        for (int ww = 0; ww < TPB / 32; ww++) s += sm[ww][threadIdx.x];
        atomicAdd(&g_S[threadIdx.x], s);
    }
    __syncthreads();   // all block atomics issued before counter bump
}

// ---------------------------------------------------------------------------
// Last-block epilogue: b update, err, convergence — fused, no extra launch.
// bar.sync makes all block writes cta-visible to thread 0; its fence.gpu then
// promotes them (fence cumulativity) before the counter atomic.
// ---------------------------------------------------------------------------
__device__ __forceinline__ void finalize_update(int first) {
    __shared__ int is_last;
    if (threadIdx.x == 0) {
        __threadfence();
        unsigned t = atomicAdd(&g_done, 1u);
        is_last = (t == (unsigned)(gridDim.x - 1));
    }
    __syncthreads();
    if (is_last && threadIdx.x == 0) {
        __threadfence();      // acquire: see all blocks' g_S atomics
        g_done = 0;
        const double FI = 1.0 / 1.1;   // gamma/(gamma+eps)
        double nb[K];
        double err2 = 0.0;
#pragma unroll
        for (int j = 0; j < K; j++) {
            double v = (double)NR * c_Pb[j] / g_S[j];   // b_j = Pb_j / (Q^T a)_j
            nb[j] = pow(v, FI);                          // SEMI_USE exponent
            double d = nb[j] - g_b[j];
            err2 += d * d;
        }
        if (first) err2 += 0.015625;   // b[7]: 1/8 -> 0 on iteration 1
#pragma unroll
        for (int j = 0; j < K; j++) {
            g_fbprev[j] = (float)g_b[j];
            g_b[j] = nb[j];
            g_fb[j] = (float)nb[j];
            g_S[j] = 0.0;              // reset for next pass
        }
        if (sqrt(err2) <= 1e-6) g_conv = 1;
    }
}

// ---------------------------------------------------------------------------
__global__ void k_init() {
    int j = threadIdx.x;
    if (j < K) {
        g_S[j] = 0.0;
        g_b[j] = 0.125;
        g_fb[j] = 0.125f;
        g_fbprev[j] = 0.125f;
    }
    if (j == 0) { g_conv = 0; g_done = 0; }
}

// ---------------------------------------------------------------------------
// Precompute E + fused Sinkhorn iteration 1 (the only one needing r_i, which
// stays in a register and is never stored).
// Iter-1: dot_i = (1/8)(r_i*sumE_i + 1);  T_j = sum_i 8*r_i*E_ij/(r_i*sumE_i+1)
// ---------------------------------------------------------------------------
__global__ void __launch_bounds__(TPB) k_pre(const float* __restrict__ P) {
    int tid = blockIdx.x * TPB + threadIdx.x;
    float acc[K];
#pragma unroll
    for (int j = 0; j < K; j++) acc[j] = 0.f;

    for (int rep = 0; rep < REPS; rep++) {
        int i = tid + rep * NTHREADS;
        const float* row = P + (size_t)i * K;
        float p[K];
#pragma unroll
        for (int j = 0; j < K; j++) p[j] = row[j];
        float m = p[0];
#pragma unroll
        for (int j = 1; j < K; j++) m = fmaxf(m, p[j]);
        float s1 = 0.f, sE = 0.f;
        float E[K];
#pragma unroll
        for (int j = 0; j < K; j++) {
            float t = expf(p[j] - m);          // softmax numerator (unnormed)
            s1 += t;
            float t2 = t * t, t4 = t2 * t2, t8 = t4 * t4;
            E[j] = t8 * t2;                    // exp(10*(p-m)) = t^10
            sE += E[j];
            g_E[(size_t)j * NR + i] = E[j];    // column-major, coalesced
        }
        float s2 = s1 * s1, s4 = s2 * s2, s8 = s4 * s4, s10 = s8 * s2;
        float r = 1.f / s10;                   // r_i = s1^-10 in (3.5e-9, 1]
        float w = 8.f * r / (r * sE + 1.f);
#pragma unroll
        for (int j = 0; j < K; j++) acc[j] += w * E[j];
    }
    block_reduce_atomic(acc);
    finalize_update(1);
}

// ---------------------------------------------------------------------------
// Sinkhorn iteration t>=2: T_j = sum_i E_ij / (E_i . b)   (r and b[7] gone)
// L2-resident pass over E (56 MB < 126 MB L2, persists across launches).
// ---------------------------------------------------------------------------
__global__ void __launch_bounds__(TPB) k_iter() {
    if (g_conv) return;
    float b[K];
#pragma unroll
    for (int j = 0; j < K; j++) b[j] = g_fb[j];
    int tid = blockIdx.x * TPB + threadIdx.x;
    float acc[K];
#pragma unroll
    for (int j = 0; j < K; j++) acc[j] = 0.f;

#pragma unroll 4
    for (int rep = 0; rep < REPS; rep++) {
        int i = tid + rep * NTHREADS;
        float E[K];
        float dot = 0.f;
#pragma unroll
        for (int j = 0; j < K; j++) {
            E[j] = g_E[(size_t)j * NR + i];
            dot = fmaf(E[j], b[j], dot);
        }
        float inv = 1.f / dot;                 // E max per row is exactly 1 -> dot > 0
#pragma unroll
        for (int j = 0; j < K; j++) acc[j] = fmaf(E[j], inv, acc[j]);
    }
    block_reduce_atomic(acc);
    finalize_update(0);
}

// ---------------------------------------------------------------------------
// plan_ij = E_ij * b_j / (E_i . b_prev)   (loop always runs >=2 iters, so
// b_prev[7]=0 and r_i cancels). Output row-major [n,7] fp32.
// ---------------------------------------------------------------------------
__global__ void __launch_bounds__(TPB) k_final(float* __restrict__ out) {
    float bn[K], bp[K];
#pragma unroll
    for (int j = 0; j < K; j++) { bn[j] = g_fb[j]; bp[j] = g_fbprev[j]; }
    int tid = blockIdx.x * TPB + threadIdx.x;

#pragma unroll 2
    for (int rep = 0; rep < REPS; rep++) {
        int i = tid + rep * NTHREADS;
        float E[K];
        float dot = 0.f;
#pragma unroll
        for (int j = 0; j < K; j++) {
            E[j] = g_E[(size_t)j * NR + i];
            dot = fmaf(E[j], bp[j], dot);
        }
        float inv = 1.f / dot;
        float* o = out + (size_t)i * K;
#pragma unroll
        for (int j = 0; j < K; j++) o[j] = E[j] * bn[j] * inv;
    }
}

// ---------------------------------------------------------------------------
extern "C" void kernel_launch(void* const* d_in, const int* in_sizes, int n_in,
                              void* d_out, int out_size) {
    const float* P = (const float*)d_in[0];
    float* out = (float*)d_out;
    (void)in_sizes; (void)n_in; (void)out_size;

    k_init<<<1, 32>>>();
    k_pre<<<NBLOCKS, TPB>>>(P);          // builds E + Sinkhorn iter 1
    for (int t = 0; t < 49; t++)         // iters 2..50; no-op after convergence
        k_iter<<<NBLOCKS, TPB>>>();
    k_final<<<NBLOCKS, TPB>>>(out);
}